// round 3
// baseline (speedup 1.0000x reference)
#include <cuda_runtime.h>
#include <math.h>
#include <stdint.h>

#define Bsz  64
#define Tlen 2048
#define Hd   128
#define G4   512
#define Cout 7

// own-weight split per gate: 88 floats in registers, 40 in smem
#define REGJ 22
#define SMJ  10
#define KSPLIT (4 * REGJ)

// ---------------- device scratch ----------------
__device__ float g_v0[G4];                          // W_ih0 @ ff_w
__device__ float g_u0[G4];                          // W_ih0 @ ff_b + b0
__device__ float g_h1[(size_t)Tlen * Bsz * Hd];     // layer-0 h stream  [t][b][h]
__device__ float g_z0[(size_t)Tlen * Bsz * 256];    // layer-1 input-gate partials n in [0,256)
__device__ int   g_prog[Bsz];                       // steps completed by layer-0 CTA b
__device__ float g_pool[Bsz * 3 * Hd];

__device__ __forceinline__ float sigf(float x) { return 1.0f / (1.0f + __expf(-x)); }

__device__ __forceinline__ int ld_acq(const int* p) {
    int v;
    asm volatile("ld.global.acquire.gpu.b32 %0, [%1];" : "=r"(v) : "l"(p));
    return v;
}
__device__ __forceinline__ void st_rel(int* p, int v) {
    asm volatile("st.global.release.gpu.b32 [%0], %1;" :: "l"(p), "r"(v));
}

// ---------------- prep: fold input projection + reset progress ----------------
__global__ void prep_kernel(const float* __restrict__ Wih0, const float* __restrict__ ffw,
                            const float* __restrict__ ffb,  const float* __restrict__ b0) {
    int g = threadIdx.x;  // 512
    float v = 0.f, u = 0.f;
    #pragma unroll 4
    for (int k = 0; k < Hd; k++) {
        float w = Wih0[g * Hd + k];
        v = fmaf(w, ffw[k], v);
        u = fmaf(w, ffb[k], u);
    }
    g_v0[g] = v;
    g_u0[g] = u + b0[g];
    if (g < Bsz) g_prog[g] = 0;
}

// ---------------- fused pipelined 2-layer LSTM ----------------
// grid = 128 CTAs: blockIdx < 64 -> layer-0 role (batch b), else layer-1 role.
// Each role: own recurrent matvec (512 gates, 88 reg / 40 smem weight split,
// 2 gates per thread) + half of the layer-1 input GEMV (1 gate per thread,
// weights transposed in smem [k4][n] for conflict-free broadcast-h FMA).
__global__ __launch_bounds__(256, 1)
void fused_lstm(const float* __restrict__ Whh0, const float* __restrict__ Whh1,
                const float* __restrict__ Wih1, const float* __restrict__ b1,
                const float* __restrict__ x,    const int* __restrict__ lengths) {
    extern __shared__ float sm[];
    float4* Wsm4 = (float4*)sm;                        // SMJ*512 float4 = 80 KB
    float4* Wg4  = (float4*)(sm + SMJ * 512 * 4);      // 32*256 float4 = 128 KB
    float*  h_s  = sm + SMJ * 512 * 4 + 32 * 256 * 4;  // 128
    float*  act_s = h_s + Hd;                          // 512
    float*  aux   = act_s + G4;                        // 2048 (A: xrow, B: h1buf[0:128))

    const int  tid = threadIdx.x;
    const bool isA = (blockIdx.x < Bsz);
    const int  b   = isA ? blockIdx.x : blockIdx.x - Bsz;
    const int  g0  = tid, g1 = tid + 256;
    const float* Whh = isA ? Whh0 : Whh1;

    // ---- own recurrent weights ----
    float4 w0[REGJ], w1[REGJ];
    #pragma unroll
    for (int j = 0; j < REGJ; j++) {
        w0[j] = *(const float4*)(Whh + (size_t)g0 * Hd + 4 * j);
        w1[j] = *(const float4*)(Whh + (size_t)g1 * Hd + 4 * j);
    }
    #pragma unroll
    for (int kk = 0; kk < SMJ; kk++) {
        Wsm4[kk * 512 + g0] = *(const float4*)(Whh + (size_t)g0 * Hd + KSPLIT + 4 * kk);
        Wsm4[kk * 512 + g1] = *(const float4*)(Whh + (size_t)g1 * Hd + KSPLIT + 4 * kk);
    }

    // ---- layer-1 input GEMV half: rows [rbase, rbase+256), transposed [k4][n] ----
    const int rbase = isA ? 0 : 256;
    for (int i = tid; i < 256 * 32; i += 256) {
        int n = i & 255, k4 = i >> 8;
        Wg4[k4 * 256 + n] = *(const float4*)(Wih1 + (size_t)(rbase + n) * Hd + 4 * k4);
    }
    const float bz = b1[rbase + tid];   // bias for my gemv gate

    float vg0 = 0.f, ug0 = 0.f, vg1 = 0.f, ug1 = 0.f;
    if (isA) {
        vg0 = g_v0[g0]; ug0 = g_u0[g0];
        vg1 = g_v0[g1]; ug1 = g_u0[g1];
        for (int i = tid; i < Tlen; i += 256) aux[i] = x[(size_t)b * Tlen + i];
    }
    if (tid < Hd) h_s[tid] = 0.f;

    float cst = 0.f, sum = 0.f, mx = -INFINITY, last = 0.f;
    const int len = lengths[b];
    __syncthreads();

    const float4* h4 = (const float4*)h_s;
    const float4* x4 = (const float4*)aux;

    if (isA) {
        // ============ layer-0 role ============
        for (int t = 0; t < Tlen; t++) {
            float a00 = fmaf(aux[t], vg0, ug0), a01 = 0.f;
            float a10 = fmaf(aux[t], vg1, ug1), a11 = 0.f;
            #pragma unroll
            for (int j = 0; j < REGJ; j++) {
                float4 hv = h4[j], a = w0[j], c = w1[j];
                a00 = fmaf(hv.x, a.x, a00); a01 = fmaf(hv.y, a.y, a01);
                a00 = fmaf(hv.z, a.z, a00); a01 = fmaf(hv.w, a.w, a01);
                a10 = fmaf(hv.x, c.x, a10); a11 = fmaf(hv.y, c.y, a11);
                a10 = fmaf(hv.z, c.z, a10); a11 = fmaf(hv.w, c.w, a11);
            }
            #pragma unroll
            for (int kk = 0; kk < SMJ; kk++) {
                float4 hv = h4[REGJ + kk];
                float4 a = Wsm4[kk * 512 + g0], c = Wsm4[kk * 512 + g1];
                a00 = fmaf(hv.x, a.x, a00); a01 = fmaf(hv.y, a.y, a01);
                a00 = fmaf(hv.z, a.z, a00); a01 = fmaf(hv.w, a.w, a01);
                a10 = fmaf(hv.x, c.x, a10); a11 = fmaf(hv.y, c.y, a11);
                a10 = fmaf(hv.z, c.z, a10); a11 = fmaf(hv.w, c.w, a11);
            }
            float A0 = a00 + a01, A1 = a10 + a11;
            act_s[g0] = sigf(A0);
            act_s[g1] = (tid < 128) ? tanhf(A1) : sigf(A1);
            __syncthreads();
            if (tid < Hd) {
                float iv = act_s[tid],          fv = act_s[Hd + tid];
                float gv = act_s[2 * Hd + tid], ov = act_s[3 * Hd + tid];
                cst = fmaf(fv, cst, iv * gv);
                float h = ov * tanhf(cst);
                h_s[tid] = h;
                g_h1[((size_t)t * Bsz + b) * Hd + tid] = h;
            }
            __syncthreads();
            // gemv half over fresh h1(t)
            float z = bz;
            #pragma unroll
            for (int k4 = 0; k4 < 32; k4++) {
                float4 w = Wg4[k4 * 256 + tid], hv = h4[k4];
                z = fmaf(hv.x, w.x, z); z = fmaf(hv.y, w.y, z);
                z = fmaf(hv.z, w.z, z); z = fmaf(hv.w, w.w, z);
            }
            g_z0[((size_t)t * Bsz + b) * 256 + tid] = z;
            __threadfence();
            __syncthreads();
            if (tid == 0) st_rel(&g_prog[b], t + 1);
        }
    } else {
        // ============ layer-1 role ============
        for (int t = 0; t < Tlen; t++) {
            if (tid == 0) {
                while (ld_acq(&g_prog[b]) < t + 1) __nanosleep(64);
            }
            __syncthreads();
            // issue producer loads early; own matvec hides their latency
            float z0v = g_z0[((size_t)t * Bsz + b) * 256 + tid];
            float h1v = (tid < Hd) ? g_h1[((size_t)t * Bsz + b) * Hd + tid] : 0.f;

            float a00 = 0.f, a01 = 0.f, a10 = 0.f, a11 = 0.f;
            #pragma unroll
            for (int j = 0; j < REGJ; j++) {
                float4 hv = h4[j], a = w0[j], c = w1[j];
                a00 = fmaf(hv.x, a.x, a00); a01 = fmaf(hv.y, a.y, a01);
                a00 = fmaf(hv.z, a.z, a00); a01 = fmaf(hv.w, a.w, a01);
                a10 = fmaf(hv.x, c.x, a10); a11 = fmaf(hv.y, c.y, a11);
                a10 = fmaf(hv.z, c.z, a10); a11 = fmaf(hv.w, c.w, a11);
            }
            #pragma unroll
            for (int kk = 0; kk < SMJ; kk++) {
                float4 hv = h4[REGJ + kk];
                float4 a = Wsm4[kk * 512 + g0], c = Wsm4[kk * 512 + g1];
                a00 = fmaf(hv.x, a.x, a00); a01 = fmaf(hv.y, a.y, a01);
                a00 = fmaf(hv.z, a.z, a00); a01 = fmaf(hv.w, a.w, a01);
                a10 = fmaf(hv.x, c.x, a10); a11 = fmaf(hv.y, c.y, a11);
                a10 = fmaf(hv.z, c.z, a10); a11 = fmaf(hv.w, c.w, a11);
            }
            if (tid < Hd) aux[tid] = h1v;
            __syncthreads();
            // gemv half over h1(t)
            float z1 = bz;
            #pragma unroll
            for (int k4 = 0; k4 < 32; k4++) {
                float4 w = Wg4[k4 * 256 + tid], hv = x4[k4];
                z1 = fmaf(hv.x, w.x, z1); z1 = fmaf(hv.y, w.y, z1);
                z1 = fmaf(hv.z, w.z, z1); z1 = fmaf(hv.w, w.w, z1);
            }
            float A0 = a00 + a01 + z0v;    // gates [0,256): z0 from layer-0 CTA (bias folded)
            float A1 = a10 + a11 + z1;     // gates [256,512): local gemv + bias
            act_s[g0] = sigf(A0);
            act_s[g1] = (tid < 128) ? tanhf(A1) : sigf(A1);
            __syncthreads();
            if (tid < Hd) {
                float iv = act_s[tid],          fv = act_s[Hd + tid];
                float gv = act_s[2 * Hd + tid], ov = act_s[3 * Hd + tid];
                cst = fmaf(fv, cst, iv * gv);
                float h = ov * tanhf(cst);
                h_s[tid] = h;
                if (t < len) { sum += h; mx = fmaxf(mx, h); }
                if (t == len - 1) last = h;
            }
            __syncthreads();
        }
        if (tid < Hd) {
            g_pool[b * 384 + tid]          = sum / (float)len;
            g_pool[b * 384 + Hd + tid]     = mx;
            g_pool[b * 384 + 2 * Hd + tid] = last;
        }
    }
}

// ---------------- final linear ----------------
__global__ void final_kernel(const float* __restrict__ lw, const float* __restrict__ lb,
                             float* __restrict__ out) {
    int tid = blockIdx.x * blockDim.x + threadIdx.x;
    if (tid >= Bsz * Cout) return;
    int b = tid / Cout, c = tid % Cout;
    float s = lb[c];
    const float* p = g_pool + b * 384;
    const float* w = lw + c * 384;
    #pragma unroll 8
    for (int j = 0; j < 384; j++) s = fmaf(p[j], w[j], s);
    out[tid] = s;
}

// ---------------- launch ----------------
extern "C" void kernel_launch(void* const* d_in, const int* in_sizes, int n_in,
                              void* d_out, int out_size) {
    const float* x    = (const float*)d_in[0];
    const int*   lens = (const int*)  d_in[1];
    const float* ffw  = (const float*)d_in[2];
    const float* ffb  = (const float*)d_in[3];
    const float* Wih0 = (const float*)d_in[4];
    const float* Whh0 = (const float*)d_in[5];
    const float* b0   = (const float*)d_in[6];
    const float* Wih1 = (const float*)d_in[7];
    const float* Whh1 = (const float*)d_in[8];
    const float* b1   = (const float*)d_in[9];
    const float* lw   = (const float*)d_in[10];
    const float* lb   = (const float*)d_in[11];
    float* out = (float*)d_out;

    // smem: 80KB own weights + 128KB gemv weights + (128+512+2048)*4 B buffers
    const int SMEM = (SMJ * 512 * 4 + 32 * 256 * 4 + Hd + G4 + Tlen) * (int)sizeof(float);
    cudaFuncSetAttribute(fused_lstm, cudaFuncAttributeMaxDynamicSharedMemorySize, SMEM);

    prep_kernel<<<1, 512>>>(Wih0, ffw, ffb, b0);
    fused_lstm<<<2 * Bsz, 256, SMEM>>>(Whh0, Whh1, Wih1, b1, x, lens);
    final_kernel<<<1, 512>>>(lw, lb, out);
}

// round 4
// speedup vs baseline: 1.5240x; 1.5240x over previous
#include <cuda_runtime.h>
#include <math.h>
#include <stdint.h>

#define Bsz  64
#define Tlen 2048
#define Hd   128
#define G4   512
#define Cout 7

// ---------------- device scratch ----------------
__device__ float g_v0[G4];                          // W_ih0 @ ff_w
__device__ float g_u0[G4];                          // W_ih0 @ ff_b + b0
__device__ float g_H1[(size_t)Tlen * Bsz * Hd];     // layer-0 h stream [t][b][h]
__device__ float g_G1[(size_t)Tlen * Bsz * G4];     // layer-1 input-gate preacts [t][b][g]
__device__ float g_pool[Bsz * 3 * Hd];

__device__ __forceinline__ float sigf(float x)  { return 1.0f / (1.0f + __expf(-x)); }
__device__ __forceinline__ float tanhfast(float x) {
    // tanh(x) = 1 - 2/(exp(2x)+1)  (2 MUFU, matches sigf cost)
    return fmaf(-2.0f, 1.0f / (__expf(2.0f * x) + 1.0f), 1.0f);
}

__device__ __forceinline__ uint32_t smem_u32(const void* p) {
    uint32_t a;
    asm("{ .reg .u64 t; cvta.to.shared.u64 t, %1; cvt.u32.u64 %0, t; }" : "=r"(a) : "l"(p));
    return a;
}
__device__ __forceinline__ uint32_t mapa32(uint32_t a, uint32_t rank) {
    uint32_t d;
    asm("mapa.shared::cluster.u32 %0, %1, %2;" : "=r"(d) : "r"(a), "r"(rank));
    return d;
}
__device__ __forceinline__ void st_async_remote(uint32_t raddr, float v, uint32_t rmbar) {
    asm volatile("st.async.shared::cluster.mbarrier::complete_tx::bytes.b32 [%0], %1, [%2];"
                 :: "r"(raddr), "r"(__float_as_uint(v)), "r"(rmbar) : "memory");
}
__device__ __forceinline__ void mbar_init(uint32_t mbar, uint32_t cnt) {
    asm volatile("mbarrier.init.shared.b64 [%0], %1;" :: "r"(mbar), "r"(cnt) : "memory");
}
__device__ __forceinline__ void mbar_expect_tx(uint32_t mbar, uint32_t bytes) {
    asm volatile("mbarrier.arrive.expect_tx.shared.b64 _, [%0], %1;" :: "r"(mbar), "r"(bytes) : "memory");
}
__device__ __forceinline__ void mbar_wait(uint32_t mbar, uint32_t parity) {
    uint32_t done;
    asm volatile(
        "{\n\t.reg .pred p;\n\t"
        "mbarrier.try_wait.parity.acquire.cluster.shared::cta.b64 p, [%1], %2;\n\t"
        "selp.b32 %0, 1, 0, p;\n\t}"
        : "=r"(done) : "r"(mbar), "r"(parity) : "memory");
    if (!done) {
        asm volatile(
            "{\n\t.reg .pred P1;\n\t"
            "WL_%=:\n\t"
            "mbarrier.try_wait.parity.acquire.cluster.shared::cta.b64 P1, [%0], %1, 0x989680;\n\t"
            "@P1 bra.uni WD_%=;\n\t"
            "bra.uni WL_%=;\n\t"
            "WD_%=:\n\t}"
            :: "r"(mbar), "r"(parity) : "memory");
    }
}

// ---------------- prep ----------------
__global__ void prep_kernel(const float* __restrict__ Wih0, const float* __restrict__ ffw,
                            const float* __restrict__ ffb,  const float* __restrict__ b0) {
    int g = threadIdx.x;  // 512
    float v = 0.f, u = 0.f;
    #pragma unroll 4
    for (int k = 0; k < Hd; k++) {
        float w = Wih0[g * Hd + k];
        v = fmaf(w, ffw[k], v);
        u = fmaf(w, ffb[k], u);
    }
    g_v0[g] = v;
    g_u0[g] = u + b0[g];
}

// ---------------- cluster-split LSTM layer ----------------
// grid = 128 CTAs as 64 clusters of 2. batch = blockIdx/2, rank = blockIdx&1.
// Thread owns ONE gate g = rank*256 + tid; all 128 W_hh weights in registers.
// Per step: matvec (512-cyc issue floor) -> act -> st.async 256 floats to peer
// (mbarrier complete_tx, parity double-buffered) -> redundant h-update in both CTAs.
template <int LAYER>
__global__ __launch_bounds__(256, 1) __cluster_dims__(2, 1, 1)
void lstm_kernel(const float* __restrict__ Whh,
                 const float* __restrict__ xin,
                 const int*   __restrict__ lengths) {
    __shared__ float act[2][G4];
    __shared__ float h_s[Hd];
    __shared__ float xrow[Tlen];
    __shared__ __align__(8) unsigned long long mbar[2];

    const int tid  = threadIdx.x;
    const int rank = blockIdx.x & 1;
    const int b    = blockIdx.x >> 1;
    const int g    = rank * 256 + tid;      // global gate index

    // ---- weights fully in registers ----
    float4 w[32];
    #pragma unroll
    for (int j = 0; j < 32; j++)
        w[j] = *(const float4*)(Whh + (size_t)g * Hd + 4 * j);

    // ---- mbarriers ----
    uint32_t mb0 = smem_u32(&mbar[0]);
    uint32_t mb1 = smem_u32(&mbar[1]);
    if (tid == 0) {
        mbar_init(mb0, 1); mbar_init(mb1, 1);
        mbar_expect_tx(mb0, 1024); mbar_expect_tx(mb1, 1024);
    }
    // remote addresses (peer CTA)
    const uint32_t peer = rank ^ 1;
    const uint32_t r_act0 = mapa32(smem_u32(&act[0][g]), peer);
    const uint32_t r_act1 = mapa32(smem_u32(&act[1][g]), peer);
    const uint32_t r_mb0  = mapa32(mb0, peer);
    const uint32_t r_mb1  = mapa32(mb1, peer);

    float vg = 0.f, ug = 0.f;
    if (LAYER == 0) {
        vg = g_v0[g]; ug = g_u0[g];
        for (int i = tid; i < Tlen; i += 256) xrow[i] = xin[(size_t)b * Tlen + i];
    }
    if (tid < Hd) h_s[tid] = 0.f;
    __syncthreads();
    // peer mbars must be armed before any st.async
    asm volatile("barrier.cluster.arrive.aligned;" ::: "memory");
    asm volatile("barrier.cluster.wait.aligned;" ::: "memory");

    float cst = 0.f, sum = 0.f, mx = -INFINITY, last = 0.f;
    const int len = lengths[b];
    uint32_t ph0 = 0, ph1 = 0;

    float zn = 0.f;
    if (LAYER == 1) zn = g_G1[(size_t)b * G4 + g];   // prefetch t=0

    const float4* h4 = (const float4*)h_s;

    for (int t = 0; t < Tlen; t++) {
        const int p = t & 1;

        float a0, a1 = 0.f;
        if (LAYER == 0) {
            a0 = fmaf(xrow[t], vg, ug);
        } else {
            a0 = zn;
            if (t + 1 < Tlen) zn = g_G1[((size_t)(t + 1) * Bsz + b) * G4 + g];
        }
        #pragma unroll
        for (int j = 0; j < 32; j++) {
            float4 hv = h4[j], wv = w[j];
            a0 = fmaf(hv.x, wv.x, a0);
            a1 = fmaf(hv.y, wv.y, a1);
            a0 = fmaf(hv.z, wv.z, a0);
            a1 = fmaf(hv.w, wv.w, a1);
        }
        float A = a0 + a1;

        // activation: rank0 gates [0,256)=i,f -> sigmoid; rank1: [256,384)=g tanh, [384,512)=o sigmoid
        float av;
        if (rank == 0)           av = sigf(A);
        else if (tid < 128)      av = tanhfast(A);
        else                     av = sigf(A);

        // send to peer first (start the 215-cyc DSMEM flight ASAP), then local store
        st_async_remote(p ? r_act1 : r_act0, av, p ? r_mb1 : r_mb0);
        act[p][g] = av;
        __syncthreads();   // local half visible

        if (tid < Hd) {
            // wait for the 256 remote gate activations of this step
            if (p == 0) { mbar_wait(mb0, ph0); } else { mbar_wait(mb1, ph1); }
            if (tid == 0) {  // re-arm for use at t+2 (peer cannot send t+2 before our t+1 send)
                mbar_expect_tx(p ? mb1 : mb0, 1024);
            }
            float iv = act[p][tid],          fv = act[p][Hd + tid];
            float gv = act[p][2 * Hd + tid], ov = act[p][3 * Hd + tid];
            cst = fmaf(fv, cst, iv * gv);
            float h = ov * tanhfast(cst);
            h_s[tid] = h;
            if (LAYER == 0) {
                if (rank == 0) g_H1[((size_t)t * Bsz + b) * Hd + tid] = h;
            } else if (rank == 0) {
                if (t < len) { sum += h; mx = fmaxf(mx, h); }
                if (t == len - 1) last = h;
            }
        }
        if (p == 0) ph0 ^= 1; else ph1 ^= 1;
        __syncthreads();
    }

    if (LAYER == 1 && rank == 0 && tid < Hd) {
        g_pool[b * 384 + tid]          = sum / (float)len;
        g_pool[b * 384 + Hd + tid]     = mx;
        g_pool[b * 384 + 2 * Hd + tid] = last;
    }
    asm volatile("barrier.cluster.arrive.aligned;" ::: "memory");
    asm volatile("barrier.cluster.wait.aligned;" ::: "memory");
}

// ---------------- GEMM: G1 = H1 @ Wih1^T + b1  (M=131072, N=512, K=128) ----------------
__global__ __launch_bounds__(256)
void gemm_g1_kernel(const float* __restrict__ Wih1, const float* __restrict__ b1) {
    __shared__ float As[16][128];
    __shared__ float Bs[16][128];
    const int m0 = blockIdx.x * 128;
    const int n0 = blockIdx.y * 128;
    const int tid = threadIdx.x;
    const int tr = (tid >> 4) * 8;
    const int tc = (tid & 15) * 8;

    float acc[8][8];
    #pragma unroll
    for (int i = 0; i < 8; i++)
        #pragma unroll
        for (int j = 0; j < 8; j++) acc[i][j] = 0.f;

    for (int k0 = 0; k0 < 128; k0 += 16) {
        for (int l = tid; l < 512; l += 256) {
            int row = l >> 2, c4 = (l & 3) * 4;
            float4 v = *(const float4*)(g_H1 + (size_t)(m0 + row) * 128 + k0 + c4);
            As[c4 + 0][row] = v.x; As[c4 + 1][row] = v.y;
            As[c4 + 2][row] = v.z; As[c4 + 3][row] = v.w;
        }
        for (int l = tid; l < 512; l += 256) {
            int row = l >> 2, c4 = (l & 3) * 4;
            float4 v = *(const float4*)(Wih1 + (size_t)(n0 + row) * 128 + k0 + c4);
            Bs[c4 + 0][row] = v.x; Bs[c4 + 1][row] = v.y;
            Bs[c4 + 2][row] = v.z; Bs[c4 + 3][row] = v.w;
        }
        __syncthreads();
        #pragma unroll
        for (int kk = 0; kk < 16; kk++) {
            float4 a0 = *(const float4*)&As[kk][tr];
            float4 a1 = *(const float4*)&As[kk][tr + 4];
            float4 b0v = *(const float4*)&Bs[kk][tc];
            float4 b1v = *(const float4*)&Bs[kk][tc + 4];
            float ra[8] = {a0.x, a0.y, a0.z, a0.w, a1.x, a1.y, a1.z, a1.w};
            float rb[8] = {b0v.x, b0v.y, b0v.z, b0v.w, b1v.x, b1v.y, b1v.z, b1v.w};
            #pragma unroll
            for (int i = 0; i < 8; i++)
                #pragma unroll
                for (int j = 0; j < 8; j++)
                    acc[i][j] = fmaf(ra[i], rb[j], acc[i][j]);
        }
        __syncthreads();
    }
    #pragma unroll
    for (int i = 0; i < 8; i++) {
        #pragma unroll
        for (int j = 0; j < 8; j += 4) {
            float4 v;
            v.x = acc[i][j + 0] + b1[n0 + tc + j + 0];
            v.y = acc[i][j + 1] + b1[n0 + tc + j + 1];
            v.z = acc[i][j + 2] + b1[n0 + tc + j + 2];
            v.w = acc[i][j + 3] + b1[n0 + tc + j + 3];
            *(float4*)(g_G1 + (size_t)(m0 + tr + i) * G4 + n0 + tc + j) = v;
        }
    }
}

// ---------------- final linear ----------------
__global__ void final_kernel(const float* __restrict__ lw, const float* __restrict__ lb,
                             float* __restrict__ out) {
    int tid = blockIdx.x * blockDim.x + threadIdx.x;
    if (tid >= Bsz * Cout) return;
    int b = tid / Cout, c = tid % Cout;
    float s = lb[c];
    const float* p = g_pool + b * 384;
    const float* w = lw + c * 384;
    #pragma unroll 8
    for (int j = 0; j < 384; j++) s = fmaf(p[j], w[j], s);
    out[tid] = s;
}

// ---------------- launch ----------------
extern "C" void kernel_launch(void* const* d_in, const int* in_sizes, int n_in,
                              void* d_out, int out_size) {
    const float* x    = (const float*)d_in[0];
    const int*   lens = (const int*)  d_in[1];
    const float* ffw  = (const float*)d_in[2];
    const float* ffb  = (const float*)d_in[3];
    const float* Wih0 = (const float*)d_in[4];
    const float* Whh0 = (const float*)d_in[5];
    const float* b0   = (const float*)d_in[6];
    const float* Wih1 = (const float*)d_in[7];
    const float* Whh1 = (const float*)d_in[8];
    const float* b1   = (const float*)d_in[9];
    const float* lw   = (const float*)d_in[10];
    const float* lb   = (const float*)d_in[11];
    float* out = (float*)d_out;

    prep_kernel<<<1, 512>>>(Wih0, ffw, ffb, b0);
    lstm_kernel<0><<<2 * Bsz, 256>>>(Whh0, x, lens);
    dim3 ggrid((Tlen * Bsz) / 128, G4 / 128);
    gemm_g1_kernel<<<ggrid, 256>>>(Wih1, b1);
    lstm_kernel<1><<<2 * Bsz, 256>>>(Whh1, x, lens);
    final_kernel<<<1, 512>>>(lw, lb, out);
}